// round 11
// baseline (speedup 1.0000x reference)
#include <cuda_runtime.h>
#include <cuda_bf16.h>
#include <cuda_fp16.h>
#include <stdint.h>

#define N_NODES 50000
#define N_EDGES 1000000
#define IN_SIZE 256
#define OUT_SIZE 128
#define N_ET 3
#define N_TOT (N_ET * N_NODES)          // 150000
#define TOTAL_E (N_ET * N_EDGES)        // 3000000
#define SCAN_CHUNK 2048
#define SCAN_BLOCKS ((N_TOT + SCAN_CHUNK - 1) / SCAN_CHUNK)   // 74
#define GEMM_BX ((N_NODES + 127) / 128) // 391

// Scratch: Wh in fp16 (halves gather traffic; 38.4MB, L2-resident)
__device__ __half g_Wh[(size_t)N_ET * N_NODES * OUT_SIZE];
__device__ int   g_cnt[N_TOT];          // zeroed by scan_a after use -> stays zero
__device__ int   g_off[N_TOT + 1];
__device__ int   g_pos[N_TOT];
__device__ int   g_part[SCAN_BLOCKS];
__device__ int   g_eidx[TOTAL_E];       // src node per edge, dst-sorted

// ---------------------------------------------------------------------------
// CSR build
// ---------------------------------------------------------------------------
__global__ void hist_kernel(const int* __restrict__ edst) {
    int base = (blockIdx.x * blockDim.x + threadIdx.x) * 8;
    if (base >= TOTAL_E) return;
    if (base + 8 <= TOTAL_E && (base / N_EDGES == (base + 7) / N_EDGES)) {
        int o = (base / N_EDGES) * N_NODES;
        int4 a = *(const int4*)&edst[base];
        int4 c = *(const int4*)&edst[base + 4];
        atomicAdd(&g_cnt[o + a.x], 1);
        atomicAdd(&g_cnt[o + a.y], 1);
        atomicAdd(&g_cnt[o + a.z], 1);
        atomicAdd(&g_cnt[o + a.w], 1);
        atomicAdd(&g_cnt[o + c.x], 1);
        atomicAdd(&g_cnt[o + c.y], 1);
        atomicAdd(&g_cnt[o + c.z], 1);
        atomicAdd(&g_cnt[o + c.w], 1);
    } else {
        for (int i = base; i < base + 8 && i < TOTAL_E; i++)
            atomicAdd(&g_cnt[(i / N_EDGES) * N_NODES + __ldg(&edst[i])], 1);
    }
}

__global__ __launch_bounds__(256) void scan_a_kernel() {
    __shared__ int s[256];
    const int tid = threadIdx.x;
    const int base = blockIdx.x * SCAN_CHUNK + tid * 8;
    int v[8];
    int tsum = 0;
#pragma unroll
    for (int k = 0; k < 8; k++) {
        int i = base + k;
        v[k] = (i < N_TOT) ? g_cnt[i] : 0;
        if (i < N_TOT) g_cnt[i] = 0;        // leave zeroed for next replay
        tsum += v[k];
    }
    s[tid] = tsum;
    __syncthreads();
    for (int off = 1; off < 256; off <<= 1) {
        int t = (tid >= off) ? s[tid - off] : 0;
        __syncthreads();
        s[tid] += t;
        __syncthreads();
    }
    int run = s[tid] - tsum;
#pragma unroll
    for (int k = 0; k < 8; k++) {
        int i = base + k;
        if (i < N_TOT) g_off[i] = run;
        run += v[k];
    }
    if (tid == 255) g_part[blockIdx.x] = s[255];
}

// scan_c with scan_b fused: every block re-scans the 74-entry g_part locally.
__global__ __launch_bounds__(256) void scan_c_kernel() {
    __shared__ int sp[128];
    int tid = threadIdx.x;
    int pv = (tid < 128 && tid < SCAN_BLOCKS) ? g_part[tid] : 0;
    if (tid < 128) sp[tid] = pv;
    __syncthreads();
    if (tid < 128) {
        for (int off = 1; off < 128; off <<= 1) {
            int t = (tid >= off) ? sp[tid - off] : 0;
            __syncthreads();
            sp[tid] += t;
            __syncthreads();
        }
    } else {
        for (int off = 1; off < 128; off <<= 1) { __syncthreads(); __syncthreads(); }
    }
    // sp[] now holds inclusive prefix; exclusive(b) = sp[b] - g_part[b] -> use sp[b-1]
    int i = blockIdx.x * blockDim.x + tid;
    if (i < N_TOT) {
        int blk = i / SCAN_CHUNK;
        int add = (blk == 0) ? 0 : sp[blk - 1];
        int o = g_off[i] + add;
        g_off[i] = o;
        g_pos[i] = o;
    }
    if (blockIdx.x == 0 && tid == 0) g_off[N_TOT] = sp[SCAN_BLOCKS - 1];
}

__global__ void fill_kernel(const int* __restrict__ esrc,
                            const int* __restrict__ edst) {
    int base = (blockIdx.x * blockDim.x + threadIdx.x) * 4;
    if (base >= TOTAL_E) return;
    if (base + 4 <= TOTAL_E && (base / N_EDGES == (base + 3) / N_EDGES)) {
        int o = (base / N_EDGES) * N_NODES;
        int4 d4 = *(const int4*)&edst[base];
        int4 s4 = *(const int4*)&esrc[base];
        int p0 = atomicAdd(&g_pos[o + d4.x], 1); g_eidx[p0] = s4.x;
        int p1 = atomicAdd(&g_pos[o + d4.y], 1); g_eidx[p1] = s4.y;
        int p2 = atomicAdd(&g_pos[o + d4.z], 1); g_eidx[p2] = s4.z;
        int p3 = atomicAdd(&g_pos[o + d4.w], 1); g_eidx[p3] = s4.w;
    } else {
        for (int i = base; i < base + 4 && i < TOTAL_E; i++) {
            int et = i / N_EDGES;
            int d = __ldg(&edst[i]);
            int s = __ldg(&esrc[i]);
            int p = atomicAdd(&g_pos[et * N_NODES + d], 1);
            g_eidx[p] = s;
        }
    }
}

// ---------------------------------------------------------------------------
// bf16-split GEMM helpers
// ---------------------------------------------------------------------------
#define MMA_BF16(D, A, B)                                                     \
    asm volatile(                                                             \
        "mma.sync.aligned.m16n8k16.row.col.f32.bf16.bf16.f32 "                \
        "{%0,%1,%2,%3}, {%4,%5,%6,%7}, {%8,%9}, {%0,%1,%2,%3};"               \
        : "+f"(D[0]), "+f"(D[1]), "+f"(D[2]), "+f"(D[3])                      \
        : "r"(A[0]), "r"(A[1]), "r"(A[2]), "r"(A[3]), "r"(B[0]), "r"(B[1]))

__device__ __forceinline__ void bf16_split2(float a, float b,
                                            uint32_t& hi, uint32_t& lo) {
    __nv_bfloat162 h, l;
    h.x = __float2bfloat16(a);
    h.y = __float2bfloat16(b);
    l.x = __float2bfloat16(a - __bfloat162float(h.x));
    l.y = __float2bfloat16(b - __bfloat162float(h.y));
    hi = *(uint32_t*)&h;
    lo = *(uint32_t*)&l;
}

#define PS 12   // pair-stride: 8 k-pairs + 4 pad

// ---------------------------------------------------------------------------
// Per-etype GEMM: Wh[et] = x @ W[et], split-bf16 (3x m16n8k16 per k-tile).
// ---------------------------------------------------------------------------
__global__ __launch_bounds__(256, 2) void gemm_kernel(const float* __restrict__ x,
                                                      const float* __restrict__ W,
                                                      int et) {
    const int m0 = blockIdx.x * 128;
    const int tid = threadIdx.x;
    const int wid = tid >> 5;
    const int lane = tid & 31;
    const int m_off = (wid >> 1) * 32;
    const int n_off = (wid & 1) * 64;
    const int gq = lane >> 2;
    const int tg = lane & 3;

    __shared__ uint32_t Ah[128 * PS];
    __shared__ uint32_t Al[128 * PS];
    __shared__ uint32_t Bh[128 * PS];
    __shared__ uint32_t Bl[128 * PS];

    const float* Wt = W + (size_t)et * IN_SIZE * OUT_SIZE;

    float acc[2][8][4];
#pragma unroll
    for (int i = 0; i < 2; i++)
#pragma unroll
        for (int j = 0; j < 8; j++)
#pragma unroll
            for (int c = 0; c < 4; c++) acc[i][j][c] = 0.0f;

    const int wn = tid & 127;
    const int wkh = tid >> 7;

    for (int k0 = 0; k0 < IN_SIZE; k0 += 16) {
#pragma unroll
        for (int i = 0; i < 2; i++) {
            int f4 = tid + i * 256;
            int row = f4 >> 2;
            int kc = (f4 & 3) * 4;
            int gm = m0 + row;
            float4 v = make_float4(0.f, 0.f, 0.f, 0.f);
            if (gm < N_NODES) v = *(const float4*)&x[(size_t)gm * IN_SIZE + k0 + kc];
            uint32_t h0, l0, h1, l1;
            bf16_split2(v.x, v.y, h0, l0);
            bf16_split2(v.z, v.w, h1, l1);
            int p = row * PS + (kc >> 1);
            Ah[p] = h0; Ah[p + 1] = h1;
            Al[p] = l0; Al[p + 1] = l1;
        }
        {
            float w[8];
#pragma unroll
            for (int i = 0; i < 8; i++)
                w[i] = __ldg(&Wt[(size_t)(k0 + wkh * 8 + i) * OUT_SIZE + wn]);
            int p = wn * PS + wkh * 4;
#pragma unroll
            for (int q = 0; q < 4; q++) {
                uint32_t h, l;
                bf16_split2(w[2 * q], w[2 * q + 1], h, l);
                Bh[p + q] = h;
                Bl[p + q] = l;
            }
        }
        __syncthreads();

        uint32_t ahi[2][4], alo[2][4];
#pragma unroll
        for (int mf = 0; mf < 2; mf++) {
            int r = (m_off + mf * 16 + gq) * PS;
            ahi[mf][0] = Ah[r + tg];
            ahi[mf][1] = Ah[r + 8 * PS + tg];
            ahi[mf][2] = Ah[r + 4 + tg];
            ahi[mf][3] = Ah[r + 8 * PS + 4 + tg];
            alo[mf][0] = Al[r + tg];
            alo[mf][1] = Al[r + 8 * PS + tg];
            alo[mf][2] = Al[r + 4 + tg];
            alo[mf][3] = Al[r + 8 * PS + 4 + tg];
        }
#pragma unroll
        for (int nf = 0; nf < 8; nf++) {
            int n = (n_off + nf * 8 + gq) * PS;
            uint32_t bhi[2], blo[2];
            bhi[0] = Bh[n + tg];
            bhi[1] = Bh[n + 4 + tg];
            blo[0] = Bl[n + tg];
            blo[1] = Bl[n + 4 + tg];
#pragma unroll
            for (int mf = 0; mf < 2; mf++) {
                MMA_BF16(acc[mf][nf], ahi[mf], bhi);
                MMA_BF16(acc[mf][nf], ahi[mf], blo);
                MMA_BF16(acc[mf][nf], alo[mf], bhi);
            }
        }
        __syncthreads();
    }

    __half* dst = g_Wh + (size_t)et * N_NODES * OUT_SIZE;
#pragma unroll
    for (int mf = 0; mf < 2; mf++) {
#pragma unroll
        for (int nf = 0; nf < 8; nf++) {
            int row = m0 + m_off + mf * 16 + gq;
            int col = n_off + nf * 8 + tg * 2;
            if (row < N_NODES) {
                *(__half2*)&dst[(size_t)row * OUT_SIZE + col] =
                    __floats2half2_rn(acc[mf][nf][0], acc[mf][nf][1]);
            }
            if (row + 8 < N_NODES) {
                *(__half2*)&dst[(size_t)(row + 8) * OUT_SIZE + col] =
                    __floats2half2_rn(acc[mf][nf][2], acc[mf][nf][3]);
            }
        }
    }
}

// ---------------------------------------------------------------------------
// Per-etype gather + mean + bias: 16-deep MLP, then 8, then 1.
// ---------------------------------------------------------------------------
__global__ __launch_bounds__(256) void gather_kernel(float* __restrict__ out,
                                                     const float* __restrict__ b,
                                                     int et) {
    const int wid = threadIdx.x >> 5;
    const int lane = threadIdx.x & 31;
    const int n = blockIdx.x * 8 + wid;
    if (n >= N_NODES) return;

    const int base = et * N_NODES + n;
    const int beg = __ldg(&g_off[base]);
    const int end = __ldg(&g_off[base + 1]);

    const __half* wh = g_Wh + (size_t)et * N_NODES * OUT_SIZE;
    float4 a0 = make_float4(0.f, 0.f, 0.f, 0.f);
    float4 a1 = make_float4(0.f, 0.f, 0.f, 0.f);

#define ACC(A, U)                                                            \
    {                                                                        \
        float2 f0 = __half22float2(*(const __half2*)&U.x);                   \
        float2 f1 = __half22float2(*(const __half2*)&U.y);                   \
        A.x += f0.x; A.y += f0.y; A.z += f1.x; A.w += f1.y;                  \
    }

    int j = beg;
    for (; j + 16 <= end; j += 16) {
        int s[16];
#pragma unroll
        for (int k = 0; k < 16; k++) s[k] = __ldg(&g_eidx[j + k]);
        uint2 u[16];
#pragma unroll
        for (int k = 0; k < 16; k++)
            u[k] = __ldg((const uint2*)&wh[(size_t)s[k] * OUT_SIZE + lane * 4]);
#pragma unroll
        for (int k = 0; k < 8; k++) ACC(a0, u[k])
#pragma unroll
        for (int k = 8; k < 16; k++) ACC(a1, u[k])
    }
    for (; j + 8 <= end; j += 8) {
        int s[8];
#pragma unroll
        for (int k = 0; k < 8; k++) s[k] = __ldg(&g_eidx[j + k]);
        uint2 u[8];
#pragma unroll
        for (int k = 0; k < 8; k++)
            u[k] = __ldg((const uint2*)&wh[(size_t)s[k] * OUT_SIZE + lane * 4]);
#pragma unroll
        for (int k = 0; k < 4; k++) ACC(a0, u[k])
#pragma unroll
        for (int k = 4; k < 8; k++) ACC(a1, u[k])
    }
    for (; j < end; j++) {
        int s = __ldg(&g_eidx[j]);
        uint2 u = __ldg((const uint2*)&wh[(size_t)s * OUT_SIZE + lane * 4]);
        ACC(a0, u)
    }
#undef ACC
    a0.x += a1.x; a0.y += a1.y; a0.z += a1.z; a0.w += a1.w;

    float4 r;
    int cnt = end - beg;
    if (cnt > 0) {
        float inv = 1.0f / (float)cnt;
        float4 bb = __ldg(&((const float4*)b)[et * 32 + lane]);
        r.x = a0.x * inv + bb.x;
        r.y = a0.y * inv + bb.y;
        r.z = a0.z * inv + bb.z;
        r.w = a0.w * inv + bb.w;
    } else {
        r = make_float4(0.f, 0.f, 0.f, 0.f);
    }
    ((float4*)out)[((size_t)n * N_ET + et) * 32 + lane] = r;
}

// ---------------------------------------------------------------------------
// Two-stream schedule, gather tail balanced 2/1:
//   s_csr    : hist -> scan_a -> scan_c(fused) -> fill
//              -> (wait gemm0) gather0 -> (wait gemm2) gather2
//   stream 0 : gemm0 -> gemm1 -> gemm2 -> (wait fill) gather1
// ---------------------------------------------------------------------------
extern "C" void kernel_launch(void* const* d_in, const int* in_sizes, int n_in,
                              void* d_out, int out_size) {
    const float* x    = (const float*)d_in[0];
    const int*   esrc = (const int*)d_in[1];
    const int*   edst = (const int*)d_in[2];
    const float* W    = (const float*)d_in[3];
    const float* b    = (const float*)d_in[4];
    float* out = (float*)d_out;

    static cudaStream_t s_csr = nullptr;
    static cudaEvent_t ev_fork = nullptr, ev_fill = nullptr, ev_done = nullptr;
    static cudaEvent_t ev_g0 = nullptr, ev_g2 = nullptr;
    if (s_csr == nullptr) {
        cudaStreamCreateWithFlags(&s_csr, cudaStreamNonBlocking);
        cudaEventCreateWithFlags(&ev_fork, cudaEventDisableTiming);
        cudaEventCreateWithFlags(&ev_fill, cudaEventDisableTiming);
        cudaEventCreateWithFlags(&ev_done, cudaEventDisableTiming);
        cudaEventCreateWithFlags(&ev_g0, cudaEventDisableTiming);
        cudaEventCreateWithFlags(&ev_g2, cudaEventDisableTiming);
    }

    // Fork
    cudaEventRecord(ev_fork, 0);
    cudaStreamWaitEvent(s_csr, ev_fork, 0);

    // CSR build on s_csr (4 kernels; scan_b fused into scan_c)
    hist_kernel<<<(TOTAL_E / 8 + 255) / 256, 256, 0, s_csr>>>(edst);
    scan_a_kernel<<<SCAN_BLOCKS, 256, 0, s_csr>>>();
    scan_c_kernel<<<(N_TOT + 255) / 256, 256, 0, s_csr>>>();
    fill_kernel<<<(TOTAL_E / 4 + 255) / 256, 256, 0, s_csr>>>(esrc, edst);
    cudaEventRecord(ev_fill, s_csr);

    // GEMMs on stream 0
    gemm_kernel<<<GEMM_BX, 256>>>(x, W, 0);
    cudaEventRecord(ev_g0, 0);
    gemm_kernel<<<GEMM_BX, 256>>>(x, W, 1);
    gemm_kernel<<<GEMM_BX, 256>>>(x, W, 2);
    cudaEventRecord(ev_g2, 0);

    // s_csr consumes etypes 0 and 2
    cudaStreamWaitEvent(s_csr, ev_g0, 0);
    gather_kernel<<<(N_NODES + 7) / 8, 256, 0, s_csr>>>(out, b, 0);
    cudaStreamWaitEvent(s_csr, ev_g2, 0);
    gather_kernel<<<(N_NODES + 7) / 8, 256, 0, s_csr>>>(out, b, 2);
    cudaEventRecord(ev_done, s_csr);

    // stream 0 consumes etype 1 (program order covers gemm1 dependency)
    cudaStreamWaitEvent(0, ev_fill, 0);
    gather_kernel<<<(N_NODES + 7) / 8, 256>>>(out, b, 1);

    // Join
    cudaStreamWaitEvent(0, ev_done, 0);
}

// round 12
// speedup vs baseline: 1.3697x; 1.3697x over previous
#include <cuda_runtime.h>
#include <cuda_bf16.h>
#include <cuda_fp16.h>
#include <stdint.h>

#define N_NODES 50000
#define N_EDGES 1000000
#define IN_SIZE 256
#define OUT_SIZE 128
#define N_ET 3
#define N_TOT (N_ET * N_NODES)          // 150000
#define TOTAL_E (N_ET * N_EDGES)        // 3000000
#define ET_CHUNK 2048
#define ET_SCAN_BLOCKS ((N_NODES + ET_CHUNK - 1) / ET_CHUNK)   // 25
#define GEMM_BX ((N_NODES + 127) / 128) // 391

// Scratch: Wh in fp16 (halves gather traffic; 38.4MB, L2-resident)
__device__ __half g_Wh[(size_t)N_ET * N_NODES * OUT_SIZE];
__device__ int   g_cnt[N_TOT];          // zeroed by scan_a after use -> stays zero
__device__ int   g_off[N_TOT + 1];
__device__ int   g_pos[N_TOT];
__device__ int   g_part[N_ET * 32];
__device__ int   g_eidx[TOTAL_E];       // src node per edge, dst-sorted (global offsets)

// ---------------------------------------------------------------------------
// Per-etype CSR build (each etype's chain is independent -> pipelined)
// ---------------------------------------------------------------------------
__global__ void hist_et_kernel(const int* __restrict__ edst, int et) {
    int base = (blockIdx.x * blockDim.x + threadIdx.x) * 4;   // local edge idx
    if (base >= N_EDGES) return;
    const int* ed = edst + (size_t)et * N_EDGES;
    int o = et * N_NODES;
    int4 d4 = *(const int4*)&ed[base];    // N_EDGES % 4 == 0
    atomicAdd(&g_cnt[o + d4.x], 1);
    atomicAdd(&g_cnt[o + d4.y], 1);
    atomicAdd(&g_cnt[o + d4.z], 1);
    atomicAdd(&g_cnt[o + d4.w], 1);
}

__global__ __launch_bounds__(256) void scan_a_et_kernel(int et) {
    __shared__ int s[256];
    const int tid = threadIdx.x;
    const int base = blockIdx.x * ET_CHUNK + tid * 8;   // local node idx
    const int goff = et * N_NODES;
    int v[8];
    int tsum = 0;
#pragma unroll
    for (int k = 0; k < 8; k++) {
        int i = base + k;
        v[k] = (i < N_NODES) ? g_cnt[goff + i] : 0;
        if (i < N_NODES) g_cnt[goff + i] = 0;   // leave zeroed for next replay
        tsum += v[k];
    }
    s[tid] = tsum;
    __syncthreads();
    for (int off = 1; off < 256; off <<= 1) {
        int t = (tid >= off) ? s[tid - off] : 0;
        __syncthreads();
        s[tid] += t;
        __syncthreads();
    }
    int run = s[tid] - tsum;    // exclusive prefix within chunk
#pragma unroll
    for (int k = 0; k < 8; k++) {
        int i = base + k;
        if (i < N_NODES) g_off[goff + i] = run;
        run += v[k];
    }
    if (tid == 255) g_part[et * 32 + blockIdx.x] = s[255];
}

// Apply chunk offsets (25-entry part scan done serially by thread 0 per block)
// and globalize with et*N_EDGES. Also writes the etype's end boundary.
__global__ __launch_bounds__(256) void scan_c_et_kernel(int et) {
    __shared__ int sp[ET_SCAN_BLOCKS];
    int tid = threadIdx.x;
    if (tid == 0) {
        int run = 0;
        for (int k = 0; k < ET_SCAN_BLOCKS; k++) {
            int t = g_part[et * 32 + k];
            sp[k] = run;                 // exclusive prefix of chunk totals
            run += t;
        }
    }
    __syncthreads();
    int i = blockIdx.x * blockDim.x + tid;   // local node idx
    if (i < N_NODES) {
        int g = et * N_NODES + i;
        int o = g_off[g] + sp[i / ET_CHUNK] + et * N_EDGES;
        g_off[g] = o;
        g_pos[g] = o;
    }
    if (blockIdx.x == 0 && tid == 0)
        g_off[(et + 1) * N_NODES] = (et + 1) * N_EDGES;   // boundary for gather(et)
}

__global__ void fill_et_kernel(const int* __restrict__ esrc,
                               const int* __restrict__ edst, int et) {
    int base = (blockIdx.x * blockDim.x + threadIdx.x) * 4;
    if (base >= N_EDGES) return;
    const int* ed = edst + (size_t)et * N_EDGES;
    const int* es = esrc + (size_t)et * N_EDGES;
    int o = et * N_NODES;
    int4 d4 = *(const int4*)&ed[base];
    int4 s4 = *(const int4*)&es[base];
    int p0 = atomicAdd(&g_pos[o + d4.x], 1); g_eidx[p0] = s4.x;
    int p1 = atomicAdd(&g_pos[o + d4.y], 1); g_eidx[p1] = s4.y;
    int p2 = atomicAdd(&g_pos[o + d4.z], 1); g_eidx[p2] = s4.z;
    int p3 = atomicAdd(&g_pos[o + d4.w], 1); g_eidx[p3] = s4.w;
}

// ---------------------------------------------------------------------------
// bf16-split GEMM helpers
// ---------------------------------------------------------------------------
#define MMA_BF16(D, A, B)                                                     \
    asm volatile(                                                             \
        "mma.sync.aligned.m16n8k16.row.col.f32.bf16.bf16.f32 "                \
        "{%0,%1,%2,%3}, {%4,%5,%6,%7}, {%8,%9}, {%0,%1,%2,%3};"               \
        : "+f"(D[0]), "+f"(D[1]), "+f"(D[2]), "+f"(D[3])                      \
        : "r"(A[0]), "r"(A[1]), "r"(A[2]), "r"(A[3]), "r"(B[0]), "r"(B[1]))

__device__ __forceinline__ void bf16_split2(float a, float b,
                                            uint32_t& hi, uint32_t& lo) {
    __nv_bfloat162 h, l;
    h.x = __float2bfloat16(a);
    h.y = __float2bfloat16(b);
    l.x = __float2bfloat16(a - __bfloat162float(h.x));
    l.y = __float2bfloat16(b - __bfloat162float(h.y));
    hi = *(uint32_t*)&h;
    lo = *(uint32_t*)&l;
}

#define PS 12   // pair-stride: 8 k-pairs + 4 pad

// ---------------------------------------------------------------------------
// Per-etype GEMM: Wh[et] = x @ W[et], split-bf16 (3x m16n8k16 per k-tile).
// ---------------------------------------------------------------------------
__global__ __launch_bounds__(256, 2) void gemm_kernel(const float* __restrict__ x,
                                                      const float* __restrict__ W,
                                                      int et) {
    const int m0 = blockIdx.x * 128;
    const int tid = threadIdx.x;
    const int wid = tid >> 5;
    const int lane = tid & 31;
    const int m_off = (wid >> 1) * 32;
    const int n_off = (wid & 1) * 64;
    const int gq = lane >> 2;
    const int tg = lane & 3;

    __shared__ uint32_t Ah[128 * PS];
    __shared__ uint32_t Al[128 * PS];
    __shared__ uint32_t Bh[128 * PS];
    __shared__ uint32_t Bl[128 * PS];

    const float* Wt = W + (size_t)et * IN_SIZE * OUT_SIZE;

    float acc[2][8][4];
#pragma unroll
    for (int i = 0; i < 2; i++)
#pragma unroll
        for (int j = 0; j < 8; j++)
#pragma unroll
            for (int c = 0; c < 4; c++) acc[i][j][c] = 0.0f;

    const int wn = tid & 127;
    const int wkh = tid >> 7;

    for (int k0 = 0; k0 < IN_SIZE; k0 += 16) {
#pragma unroll
        for (int i = 0; i < 2; i++) {
            int f4 = tid + i * 256;
            int row = f4 >> 2;
            int kc = (f4 & 3) * 4;
            int gm = m0 + row;
            float4 v = make_float4(0.f, 0.f, 0.f, 0.f);
            if (gm < N_NODES) v = *(const float4*)&x[(size_t)gm * IN_SIZE + k0 + kc];
            uint32_t h0, l0, h1, l1;
            bf16_split2(v.x, v.y, h0, l0);
            bf16_split2(v.z, v.w, h1, l1);
            int p = row * PS + (kc >> 1);
            Ah[p] = h0; Ah[p + 1] = h1;
            Al[p] = l0; Al[p + 1] = l1;
        }
        {
            float w[8];
#pragma unroll
            for (int i = 0; i < 8; i++)
                w[i] = __ldg(&Wt[(size_t)(k0 + wkh * 8 + i) * OUT_SIZE + wn]);
            int p = wn * PS + wkh * 4;
#pragma unroll
            for (int q = 0; q < 4; q++) {
                uint32_t h, l;
                bf16_split2(w[2 * q], w[2 * q + 1], h, l);
                Bh[p + q] = h;
                Bl[p + q] = l;
            }
        }
        __syncthreads();

        uint32_t ahi[2][4], alo[2][4];
#pragma unroll
        for (int mf = 0; mf < 2; mf++) {
            int r = (m_off + mf * 16 + gq) * PS;
            ahi[mf][0] = Ah[r + tg];
            ahi[mf][1] = Ah[r + 8 * PS + tg];
            ahi[mf][2] = Ah[r + 4 + tg];
            ahi[mf][3] = Ah[r + 8 * PS + 4 + tg];
            alo[mf][0] = Al[r + tg];
            alo[mf][1] = Al[r + 8 * PS + tg];
            alo[mf][2] = Al[r + 4 + tg];
            alo[mf][3] = Al[r + 8 * PS + 4 + tg];
        }
#pragma unroll
        for (int nf = 0; nf < 8; nf++) {
            int n = (n_off + nf * 8 + gq) * PS;
            uint32_t bhi[2], blo[2];
            bhi[0] = Bh[n + tg];
            bhi[1] = Bh[n + 4 + tg];
            blo[0] = Bl[n + tg];
            blo[1] = Bl[n + 4 + tg];
#pragma unroll
            for (int mf = 0; mf < 2; mf++) {
                MMA_BF16(acc[mf][nf], ahi[mf], bhi);
                MMA_BF16(acc[mf][nf], ahi[mf], blo);
                MMA_BF16(acc[mf][nf], alo[mf], bhi);
            }
        }
        __syncthreads();
    }

    __half* dst = g_Wh + (size_t)et * N_NODES * OUT_SIZE;
#pragma unroll
    for (int mf = 0; mf < 2; mf++) {
#pragma unroll
        for (int nf = 0; nf < 8; nf++) {
            int row = m0 + m_off + mf * 16 + gq;
            int col = n_off + nf * 8 + tg * 2;
            if (row < N_NODES) {
                *(__half2*)&dst[(size_t)row * OUT_SIZE + col] =
                    __floats2half2_rn(acc[mf][nf][0], acc[mf][nf][1]);
            }
            if (row + 8 < N_NODES) {
                *(__half2*)&dst[(size_t)(row + 8) * OUT_SIZE + col] =
                    __floats2half2_rn(acc[mf][nf][2], acc[mf][nf][3]);
            }
        }
    }
}

// ---------------------------------------------------------------------------
// Per-etype gather + mean + bias: 16-deep MLP, then 8, then 1. (round-10 exact)
// ---------------------------------------------------------------------------
__global__ __launch_bounds__(256) void gather_kernel(float* __restrict__ out,
                                                     const float* __restrict__ b,
                                                     int et) {
    const int wid = threadIdx.x >> 5;
    const int lane = threadIdx.x & 31;
    const int n = blockIdx.x * 8 + wid;
    if (n >= N_NODES) return;

    const int base = et * N_NODES + n;
    const int beg = __ldg(&g_off[base]);
    const int end = __ldg(&g_off[base + 1]);

    const __half* wh = g_Wh + (size_t)et * N_NODES * OUT_SIZE;
    float4 a0 = make_float4(0.f, 0.f, 0.f, 0.f);
    float4 a1 = make_float4(0.f, 0.f, 0.f, 0.f);

#define ACC(A, U)                                                            \
    {                                                                        \
        float2 f0 = __half22float2(*(const __half2*)&U.x);                   \
        float2 f1 = __half22float2(*(const __half2*)&U.y);                   \
        A.x += f0.x; A.y += f0.y; A.z += f1.x; A.w += f1.y;                  \
    }

    int j = beg;
    for (; j + 16 <= end; j += 16) {
        int s[16];
#pragma unroll
        for (int k = 0; k < 16; k++) s[k] = __ldg(&g_eidx[j + k]);
        uint2 u[16];
#pragma unroll
        for (int k = 0; k < 16; k++)
            u[k] = __ldg((const uint2*)&wh[(size_t)s[k] * OUT_SIZE + lane * 4]);
#pragma unroll
        for (int k = 0; k < 8; k++) ACC(a0, u[k])
#pragma unroll
        for (int k = 8; k < 16; k++) ACC(a1, u[k])
    }
    for (; j + 8 <= end; j += 8) {
        int s[8];
#pragma unroll
        for (int k = 0; k < 8; k++) s[k] = __ldg(&g_eidx[j + k]);
        uint2 u[8];
#pragma unroll
        for (int k = 0; k < 8; k++)
            u[k] = __ldg((const uint2*)&wh[(size_t)s[k] * OUT_SIZE + lane * 4]);
#pragma unroll
        for (int k = 0; k < 4; k++) ACC(a0, u[k])
#pragma unroll
        for (int k = 4; k < 8; k++) ACC(a1, u[k])
    }
    for (; j < end; j++) {
        int s = __ldg(&g_eidx[j]);
        uint2 u = __ldg((const uint2*)&wh[(size_t)s * OUT_SIZE + lane * 4]);
        ACC(a0, u)
    }
#undef ACC
    a0.x += a1.x; a0.y += a1.y; a0.z += a1.z; a0.w += a1.w;

    float4 r;
    int cnt = end - beg;
    if (cnt > 0) {
        float inv = 1.0f / (float)cnt;
        float4 bb = __ldg(&((const float4*)b)[et * 32 + lane]);
        r.x = a0.x * inv + bb.x;
        r.y = a0.y * inv + bb.y;
        r.z = a0.z * inv + bb.z;
        r.w = a0.w * inv + bb.w;
    } else {
        r = make_float4(0.f, 0.f, 0.f, 0.f);
    }
    ((float4*)out)[((size_t)n * N_ET + et) * 32 + lane] = r;
}

// ---------------------------------------------------------------------------
// Per-etype pipelined CSR + gathers, 2 streams / 5 events (round-10 budget):
//   s_csr    : CSR0 -> [ev_f0] -> CSR1 -> CSR2 -> [ev_f2] -> (wait gemm1) gather1
//   stream 0 : gemm0 -> gemm1 [ev_g1] -> gemm2
//              -> (wait f0) gather0 -> (wait f2) gather2
// ---------------------------------------------------------------------------
extern "C" void kernel_launch(void* const* d_in, const int* in_sizes, int n_in,
                              void* d_out, int out_size) {
    const float* x    = (const float*)d_in[0];
    const int*   esrc = (const int*)d_in[1];
    const int*   edst = (const int*)d_in[2];
    const float* W    = (const float*)d_in[3];
    const float* b    = (const float*)d_in[4];
    float* out = (float*)d_out;

    static cudaStream_t s_csr = nullptr;
    static cudaEvent_t ev_fork = nullptr, ev_f0 = nullptr, ev_f2 = nullptr;
    static cudaEvent_t ev_g1 = nullptr, ev_done = nullptr;
    if (s_csr == nullptr) {
        cudaStreamCreateWithFlags(&s_csr, cudaStreamNonBlocking);
        cudaEventCreateWithFlags(&ev_fork, cudaEventDisableTiming);
        cudaEventCreateWithFlags(&ev_f0, cudaEventDisableTiming);
        cudaEventCreateWithFlags(&ev_f2, cudaEventDisableTiming);
        cudaEventCreateWithFlags(&ev_g1, cudaEventDisableTiming);
        cudaEventCreateWithFlags(&ev_done, cudaEventDisableTiming);
    }

    const int HIST_B = (N_EDGES / 4 + 255) / 256;   // 977
    const int SCANC_B = (N_NODES + 255) / 256;      // 196

    // Fork
    cudaEventRecord(ev_fork, 0);
    cudaStreamWaitEvent(s_csr, ev_fork, 0);

    // Per-etype CSR chains on s_csr
    for (int e = 0; e < N_ET; e++) {
        hist_et_kernel<<<HIST_B, 256, 0, s_csr>>>(edst, e);
        scan_a_et_kernel<<<ET_SCAN_BLOCKS, 256, 0, s_csr>>>(e);
        scan_c_et_kernel<<<SCANC_B, 256, 0, s_csr>>>(e);
        fill_et_kernel<<<HIST_B, 256, 0, s_csr>>>(esrc, edst, e);
        if (e == 0) cudaEventRecord(ev_f0, s_csr);
        if (e == 2) cudaEventRecord(ev_f2, s_csr);
    }

    // GEMMs on stream 0
    gemm_kernel<<<GEMM_BX, 256>>>(x, W, 0);
    gemm_kernel<<<GEMM_BX, 256>>>(x, W, 1);
    cudaEventRecord(ev_g1, 0);
    gemm_kernel<<<GEMM_BX, 256>>>(x, W, 2);

    // stream 0 consumes etypes 0 then 2 (gemm deps by program order)
    cudaStreamWaitEvent(0, ev_f0, 0);
    gather_kernel<<<(N_NODES + 7) / 8, 256>>>(out, b, 0);
    cudaStreamWaitEvent(0, ev_f2, 0);
    gather_kernel<<<(N_NODES + 7) / 8, 256>>>(out, b, 2);

    // s_csr consumes etype 1 (fill1 by program order, gemm1 via event)
    cudaStreamWaitEvent(s_csr, ev_g1, 0);
    gather_kernel<<<(N_NODES + 7) / 8, 256, 0, s_csr>>>(out, b, 1);
    cudaEventRecord(ev_done, s_csr);

    // Join
    cudaStreamWaitEvent(0, ev_done, 0);
}

// round 13
// speedup vs baseline: 1.3713x; 1.0012x over previous
#include <cuda_runtime.h>
#include <cuda_bf16.h>
#include <cuda_fp16.h>
#include <stdint.h>

#define N_NODES 50000
#define N_EDGES 1000000
#define IN_SIZE 256
#define OUT_SIZE 128
#define N_ET 3
#define N_TOT (N_ET * N_NODES)          // 150000
#define TOTAL_E (N_ET * N_EDGES)        // 3000000
#define SCAN_CHUNK 2048
#define SCAN_BLOCKS ((N_TOT + SCAN_CHUNK - 1) / SCAN_CHUNK)   // 74
#define GEMM_BX ((N_NODES + 127) / 128) // 391
#define N_HALF 25000

// Scratch: Wh in fp16 (halves gather traffic; 38.4MB, L2-resident)
__device__ __half g_Wh[(size_t)N_ET * N_NODES * OUT_SIZE];
__device__ int   g_cnt[N_TOT];          // zeroed by scan_a after use -> stays zero
__device__ int   g_off[N_TOT + 1];
__device__ int   g_pos[N_TOT];
__device__ int   g_part[SCAN_BLOCKS];
__device__ int   g_eidx[TOTAL_E];       // src node per edge, dst-sorted

// ---------------------------------------------------------------------------
// CSR build (round-10 exact)
// ---------------------------------------------------------------------------
__global__ void hist_kernel(const int* __restrict__ edst) {
    int base = (blockIdx.x * blockDim.x + threadIdx.x) * 4;
    if (base >= TOTAL_E) return;
    if (base + 4 <= TOTAL_E) {
        int4 d4 = *(const int4*)&edst[base];
        int et0 = base / N_EDGES;
        int et3 = (base + 3) / N_EDGES;
        if (et0 == et3) {
            int o = et0 * N_NODES;
            atomicAdd(&g_cnt[o + d4.x], 1);
            atomicAdd(&g_cnt[o + d4.y], 1);
            atomicAdd(&g_cnt[o + d4.z], 1);
            atomicAdd(&g_cnt[o + d4.w], 1);
        } else {
            atomicAdd(&g_cnt[((base + 0) / N_EDGES) * N_NODES + d4.x], 1);
            atomicAdd(&g_cnt[((base + 1) / N_EDGES) * N_NODES + d4.y], 1);
            atomicAdd(&g_cnt[((base + 2) / N_EDGES) * N_NODES + d4.z], 1);
            atomicAdd(&g_cnt[((base + 3) / N_EDGES) * N_NODES + d4.w], 1);
        }
    } else {
        for (int i = base; i < TOTAL_E; i++)
            atomicAdd(&g_cnt[(i / N_EDGES) * N_NODES + __ldg(&edst[i])], 1);
    }
}

__global__ __launch_bounds__(256) void scan_a_kernel() {
    __shared__ int s[256];
    const int tid = threadIdx.x;
    const int base = blockIdx.x * SCAN_CHUNK + tid * 8;
    int v[8];
    int tsum = 0;
#pragma unroll
    for (int k = 0; k < 8; k++) {
        int i = base + k;
        v[k] = (i < N_TOT) ? g_cnt[i] : 0;
        if (i < N_TOT) g_cnt[i] = 0;        // leave zeroed for next replay
        tsum += v[k];
    }
    s[tid] = tsum;
    __syncthreads();
    for (int off = 1; off < 256; off <<= 1) {
        int t = (tid >= off) ? s[tid - off] : 0;
        __syncthreads();
        s[tid] += t;
        __syncthreads();
    }
    int run = s[tid] - tsum;
#pragma unroll
    for (int k = 0; k < 8; k++) {
        int i = base + k;
        if (i < N_TOT) g_off[i] = run;
        run += v[k];
    }
    if (tid == 255) g_part[blockIdx.x] = s[255];
}

__global__ __launch_bounds__(128) void scan_b_kernel() {
    __shared__ int s[128];
    int tid = threadIdx.x;
    int v = (tid < SCAN_BLOCKS) ? g_part[tid] : 0;
    s[tid] = v;
    __syncthreads();
    for (int off = 1; off < 128; off <<= 1) {
        int t = (tid >= off) ? s[tid - off] : 0;
        __syncthreads();
        s[tid] += t;
        __syncthreads();
    }
    if (tid < SCAN_BLOCKS) g_part[tid] = s[tid] - v;   // exclusive
    if (tid == 127) g_off[N_TOT] = s[127];
}

__global__ void scan_c_kernel() {
    int i = blockIdx.x * blockDim.x + threadIdx.x;
    if (i >= N_TOT) return;
    int o = g_off[i] + g_part[i / SCAN_CHUNK];
    g_off[i] = o;
    g_pos[i] = o;
}

__global__ void fill_kernel(const int* __restrict__ esrc,
                            const int* __restrict__ edst) {
    int base = (blockIdx.x * blockDim.x + threadIdx.x) * 4;
#pragma unroll
    for (int k = 0; k < 4; k++) {
        int i = base + k;
        if (i < TOTAL_E) {
            int et = i / N_EDGES;
            int d = __ldg(&edst[i]);
            int s = __ldg(&esrc[i]);
            int p = atomicAdd(&g_pos[et * N_NODES + d], 1);
            g_eidx[p] = s;
        }
    }
}

// ---------------------------------------------------------------------------
// bf16-split GEMM helpers
// ---------------------------------------------------------------------------
#define MMA_BF16(D, A, B)                                                     \
    asm volatile(                                                             \
        "mma.sync.aligned.m16n8k16.row.col.f32.bf16.bf16.f32 "                \
        "{%0,%1,%2,%3}, {%4,%5,%6,%7}, {%8,%9}, {%0,%1,%2,%3};"               \
        : "+f"(D[0]), "+f"(D[1]), "+f"(D[2]), "+f"(D[3])                      \
        : "r"(A[0]), "r"(A[1]), "r"(A[2]), "r"(A[3]), "r"(B[0]), "r"(B[1]))

__device__ __forceinline__ void bf16_split2(float a, float b,
                                            uint32_t& hi, uint32_t& lo) {
    __nv_bfloat162 h, l;
    h.x = __float2bfloat16(a);
    h.y = __float2bfloat16(b);
    l.x = __float2bfloat16(a - __bfloat162float(h.x));
    l.y = __float2bfloat16(b - __bfloat162float(h.y));
    hi = *(uint32_t*)&h;
    lo = *(uint32_t*)&l;
}

#define PS 12   // pair-stride: 8 k-pairs + 4 pad

// ---------------------------------------------------------------------------
// Per-etype GEMM: Wh[et] = x @ W[et], split-bf16 (3x m16n8k16 per k-tile).
// ---------------------------------------------------------------------------
__global__ __launch_bounds__(256, 2) void gemm_kernel(const float* __restrict__ x,
                                                      const float* __restrict__ W,
                                                      int et) {
    const int m0 = blockIdx.x * 128;
    const int tid = threadIdx.x;
    const int wid = tid >> 5;
    const int lane = tid & 31;
    const int m_off = (wid >> 1) * 32;
    const int n_off = (wid & 1) * 64;
    const int gq = lane >> 2;
    const int tg = lane & 3;

    __shared__ uint32_t Ah[128 * PS];
    __shared__ uint32_t Al[128 * PS];
    __shared__ uint32_t Bh[128 * PS];
    __shared__ uint32_t Bl[128 * PS];

    const float* Wt = W + (size_t)et * IN_SIZE * OUT_SIZE;

    float acc[2][8][4];
#pragma unroll
    for (int i = 0; i < 2; i++)
#pragma unroll
        for (int j = 0; j < 8; j++)
#pragma unroll
            for (int c = 0; c < 4; c++) acc[i][j][c] = 0.0f;

    const int wn = tid & 127;
    const int wkh = tid >> 7;

    for (int k0 = 0; k0 < IN_SIZE; k0 += 16) {
#pragma unroll
        for (int i = 0; i < 2; i++) {
            int f4 = tid + i * 256;
            int row = f4 >> 2;
            int kc = (f4 & 3) * 4;
            int gm = m0 + row;
            float4 v = make_float4(0.f, 0.f, 0.f, 0.f);
            if (gm < N_NODES) v = *(const float4*)&x[(size_t)gm * IN_SIZE + k0 + kc];
            uint32_t h0, l0, h1, l1;
            bf16_split2(v.x, v.y, h0, l0);
            bf16_split2(v.z, v.w, h1, l1);
            int p = row * PS + (kc >> 1);
            Ah[p] = h0; Ah[p + 1] = h1;
            Al[p] = l0; Al[p + 1] = l1;
        }
        {
            float w[8];
#pragma unroll
            for (int i = 0; i < 8; i++)
                w[i] = __ldg(&Wt[(size_t)(k0 + wkh * 8 + i) * OUT_SIZE + wn]);
            int p = wn * PS + wkh * 4;
#pragma unroll
            for (int q = 0; q < 4; q++) {
                uint32_t h, l;
                bf16_split2(w[2 * q], w[2 * q + 1], h, l);
                Bh[p + q] = h;
                Bl[p + q] = l;
            }
        }
        __syncthreads();

        uint32_t ahi[2][4], alo[2][4];
#pragma unroll
        for (int mf = 0; mf < 2; mf++) {
            int r = (m_off + mf * 16 + gq) * PS;
            ahi[mf][0] = Ah[r + tg];
            ahi[mf][1] = Ah[r + 8 * PS + tg];
            ahi[mf][2] = Ah[r + 4 + tg];
            ahi[mf][3] = Ah[r + 8 * PS + 4 + tg];
            alo[mf][0] = Al[r + tg];
            alo[mf][1] = Al[r + 8 * PS + tg];
            alo[mf][2] = Al[r + 4 + tg];
            alo[mf][3] = Al[r + 8 * PS + 4 + tg];
        }
#pragma unroll
        for (int nf = 0; nf < 8; nf++) {
            int n = (n_off + nf * 8 + gq) * PS;
            uint32_t bhi[2], blo[2];
            bhi[0] = Bh[n + tg];
            bhi[1] = Bh[n + 4 + tg];
            blo[0] = Bl[n + tg];
            blo[1] = Bl[n + 4 + tg];
#pragma unroll
            for (int mf = 0; mf < 2; mf++) {
                MMA_BF16(acc[mf][nf], ahi[mf], bhi);
                MMA_BF16(acc[mf][nf], ahi[mf], blo);
                MMA_BF16(acc[mf][nf], alo[mf], bhi);
            }
        }
        __syncthreads();
    }

    __half* dst = g_Wh + (size_t)et * N_NODES * OUT_SIZE;
#pragma unroll
    for (int mf = 0; mf < 2; mf++) {
#pragma unroll
        for (int nf = 0; nf < 8; nf++) {
            int row = m0 + m_off + mf * 16 + gq;
            int col = n_off + nf * 8 + tg * 2;
            if (row < N_NODES) {
                *(__half2*)&dst[(size_t)row * OUT_SIZE + col] =
                    __floats2half2_rn(acc[mf][nf][0], acc[mf][nf][1]);
            }
            if (row + 8 < N_NODES) {
                *(__half2*)&dst[(size_t)(row + 8) * OUT_SIZE + col] =
                    __floats2half2_rn(acc[mf][nf][2], acc[mf][nf][3]);
            }
        }
    }
}

// ---------------------------------------------------------------------------
// Per-etype gather + mean + bias over node range [n_begin, n_end).
// 16-deep MLP, then 8, then 1 (round-10 body).
// ---------------------------------------------------------------------------
__global__ __launch_bounds__(256) void gather_kernel(float* __restrict__ out,
                                                     const float* __restrict__ b,
                                                     int et, int n_begin, int n_end) {
    const int wid = threadIdx.x >> 5;
    const int lane = threadIdx.x & 31;
    const int n = n_begin + blockIdx.x * 8 + wid;
    if (n >= n_end) return;

    const int base = et * N_NODES + n;
    const int beg = __ldg(&g_off[base]);
    const int end = __ldg(&g_off[base + 1]);

    const __half* wh = g_Wh + (size_t)et * N_NODES * OUT_SIZE;
    float4 a0 = make_float4(0.f, 0.f, 0.f, 0.f);
    float4 a1 = make_float4(0.f, 0.f, 0.f, 0.f);

#define ACC(A, U)                                                            \
    {                                                                        \
        float2 f0 = __half22float2(*(const __half2*)&U.x);                   \
        float2 f1 = __half22float2(*(const __half2*)&U.y);                   \
        A.x += f0.x; A.y += f0.y; A.z += f1.x; A.w += f1.y;                  \
    }

    int j = beg;
    for (; j + 16 <= end; j += 16) {
        int s[16];
#pragma unroll
        for (int k = 0; k < 16; k++) s[k] = __ldg(&g_eidx[j + k]);
        uint2 u[16];
#pragma unroll
        for (int k = 0; k < 16; k++)
            u[k] = __ldg((const uint2*)&wh[(size_t)s[k] * OUT_SIZE + lane * 4]);
#pragma unroll
        for (int k = 0; k < 8; k++) ACC(a0, u[k])
#pragma unroll
        for (int k = 8; k < 16; k++) ACC(a1, u[k])
    }
    for (; j + 8 <= end; j += 8) {
        int s[8];
#pragma unroll
        for (int k = 0; k < 8; k++) s[k] = __ldg(&g_eidx[j + k]);
        uint2 u[8];
#pragma unroll
        for (int k = 0; k < 8; k++)
            u[k] = __ldg((const uint2*)&wh[(size_t)s[k] * OUT_SIZE + lane * 4]);
#pragma unroll
        for (int k = 0; k < 4; k++) ACC(a0, u[k])
#pragma unroll
        for (int k = 4; k < 8; k++) ACC(a1, u[k])
    }
    for (; j < end; j++) {
        int s = __ldg(&g_eidx[j]);
        uint2 u = __ldg((const uint2*)&wh[(size_t)s * OUT_SIZE + lane * 4]);
        ACC(a0, u)
    }
#undef ACC
    a0.x += a1.x; a0.y += a1.y; a0.z += a1.z; a0.w += a1.w;

    float4 r;
    int cnt = end - beg;
    if (cnt > 0) {
        float inv = 1.0f / (float)cnt;
        float4 bb = __ldg(&((const float4*)b)[et * 32 + lane]);
        r.x = a0.x * inv + bb.x;
        r.y = a0.y * inv + bb.y;
        r.z = a0.z * inv + bb.z;
        r.w = a0.w * inv + bb.w;
    } else {
        r = make_float4(0.f, 0.f, 0.f, 0.f);
    }
    ((float4*)out)[((size_t)n * N_ET + et) * 32 + lane] = r;
}

// ---------------------------------------------------------------------------
// Round-10 schedule with balanced tail (1.5 gathers per stream):
//   s_csr    : CSR chain [ev_fill] -> (wait gemm0) gather0 -> (wait gemm2) gather2a
//   stream 0 : gemm0 [ev_g0] -> gemm1 -> gemm2 [ev_g2]
//              -> (wait fill) gather1 -> gather2b
// ---------------------------------------------------------------------------
extern "C" void kernel_launch(void* const* d_in, const int* in_sizes, int n_in,
                              void* d_out, int out_size) {
    const float* x    = (const float*)d_in[0];
    const int*   esrc = (const int*)d_in[1];
    const int*   edst = (const int*)d_in[2];
    const float* W    = (const float*)d_in[3];
    const float* b    = (const float*)d_in[4];
    float* out = (float*)d_out;

    static cudaStream_t s_csr = nullptr;
    static cudaEvent_t ev_fork = nullptr, ev_fill = nullptr, ev_done = nullptr;
    static cudaEvent_t ev_g0 = nullptr, ev_g2 = nullptr;
    if (s_csr == nullptr) {
        cudaStreamCreateWithFlags(&s_csr, cudaStreamNonBlocking);
        cudaEventCreateWithFlags(&ev_fork, cudaEventDisableTiming);
        cudaEventCreateWithFlags(&ev_fill, cudaEventDisableTiming);
        cudaEventCreateWithFlags(&ev_done, cudaEventDisableTiming);
        cudaEventCreateWithFlags(&ev_g0, cudaEventDisableTiming);
        cudaEventCreateWithFlags(&ev_g2, cudaEventDisableTiming);
    }

    const int GB_FULL = (N_NODES + 7) / 8;        // 6250
    const int GB_HALF = (N_HALF + 7) / 8;         // 3125

    // Fork
    cudaEventRecord(ev_fork, 0);
    cudaStreamWaitEvent(s_csr, ev_fork, 0);

    // CSR build on s_csr (round-10 exact)
    hist_kernel<<<(TOTAL_E / 4 + 255) / 256, 256, 0, s_csr>>>(edst);
    scan_a_kernel<<<SCAN_BLOCKS, 256, 0, s_csr>>>();
    scan_b_kernel<<<1, 128, 0, s_csr>>>();
    scan_c_kernel<<<(N_TOT + 255) / 256, 256, 0, s_csr>>>();
    fill_kernel<<<(TOTAL_E / 4 + 255) / 256, 256, 0, s_csr>>>(esrc, edst);
    cudaEventRecord(ev_fill, s_csr);

    // GEMMs on stream 0
    gemm_kernel<<<GEMM_BX, 256>>>(x, W, 0);
    cudaEventRecord(ev_g0, 0);
    gemm_kernel<<<GEMM_BX, 256>>>(x, W, 1);
    gemm_kernel<<<GEMM_BX, 256>>>(x, W, 2);
    cudaEventRecord(ev_g2, 0);

    // s_csr tail: gather0 (full) + gather2 first half
    cudaStreamWaitEvent(s_csr, ev_g0, 0);
    gather_kernel<<<GB_FULL, 256, 0, s_csr>>>(out, b, 0, 0, N_NODES);
    cudaStreamWaitEvent(s_csr, ev_g2, 0);
    gather_kernel<<<GB_HALF, 256, 0, s_csr>>>(out, b, 2, 0, N_HALF);
    cudaEventRecord(ev_done, s_csr);

    // stream 0 tail: gather1 (full) + gather2 second half
    cudaStreamWaitEvent(0, ev_fill, 0);
    gather_kernel<<<GB_FULL, 256>>>(out, b, 1, 0, N_NODES);
    gather_kernel<<<GB_HALF, 256>>>(out, b, 2, N_HALF, N_NODES);

    // Join
    cudaStreamWaitEvent(0, ev_done, 0);
}

// round 14
// speedup vs baseline: 1.4599x; 1.0646x over previous
#include <cuda_runtime.h>
#include <cuda_bf16.h>
#include <cuda_fp16.h>
#include <stdint.h>

#define N_NODES 50000
#define N_EDGES 1000000
#define IN_SIZE 256
#define OUT_SIZE 128
#define N_ET 3
#define N_TOT (N_ET * N_NODES)          // 150000
#define TOTAL_E (N_ET * N_EDGES)        // 3000000
#define HALF_E (TOTAL_E / 2)            // 1500000
#define SCAN_CHUNK 2048
#define SCAN_BLOCKS ((N_TOT + SCAN_CHUNK - 1) / SCAN_CHUNK)   // 74
#define GEMM_BX ((N_NODES + 127) / 128) // 391

// Scratch: Wh in fp16 (halves gather traffic; 38.4MB, L2-resident)
__device__ __half g_Wh[(size_t)N_ET * N_NODES * OUT_SIZE];
__device__ int   g_cnt[N_TOT];          // zeroed by scan_a after use -> stays zero
__device__ int   g_off[N_TOT + 1];
__device__ int   g_pos[N_TOT];
__device__ int   g_part[SCAN_BLOCKS];
__device__ int   g_eidx[TOTAL_E];       // src node per edge, dst-sorted

// ---------------------------------------------------------------------------
// CSR build (round-10 kernels; hist takes an edge range so its two halves can
// run concurrently on the two streams)
// ---------------------------------------------------------------------------
__global__ void hist_kernel(const int* __restrict__ edst, int e_begin, int e_end) {
    int base = e_begin + (blockIdx.x * blockDim.x + threadIdx.x) * 4;
    if (base >= e_end) return;
    // e_begin/e_end are multiples of 4, so base+4 <= e_end always holds.
    int4 d4 = *(const int4*)&edst[base];
    int et0 = base / N_EDGES;
    int et3 = (base + 3) / N_EDGES;
    if (et0 == et3) {
        int o = et0 * N_NODES;
        atomicAdd(&g_cnt[o + d4.x], 1);
        atomicAdd(&g_cnt[o + d4.y], 1);
        atomicAdd(&g_cnt[o + d4.z], 1);
        atomicAdd(&g_cnt[o + d4.w], 1);
    } else {
        atomicAdd(&g_cnt[((base + 0) / N_EDGES) * N_NODES + d4.x], 1);
        atomicAdd(&g_cnt[((base + 1) / N_EDGES) * N_NODES + d4.y], 1);
        atomicAdd(&g_cnt[((base + 2) / N_EDGES) * N_NODES + d4.z], 1);
        atomicAdd(&g_cnt[((base + 3) / N_EDGES) * N_NODES + d4.w], 1);
    }
}

__global__ __launch_bounds__(256) void scan_a_kernel() {
    __shared__ int s[256];
    const int tid = threadIdx.x;
    const int base = blockIdx.x * SCAN_CHUNK + tid * 8;
    int v[8];
    int tsum = 0;
#pragma unroll
    for (int k = 0; k < 8; k++) {
        int i = base + k;
        v[k] = (i < N_TOT) ? g_cnt[i] : 0;
        if (i < N_TOT) g_cnt[i] = 0;        // leave zeroed for next replay
        tsum += v[k];
    }
    s[tid] = tsum;
    __syncthreads();
    for (int off = 1; off < 256; off <<= 1) {
        int t = (tid >= off) ? s[tid - off] : 0;
        __syncthreads();
        s[tid] += t;
        __syncthreads();
    }
    int run = s[tid] - tsum;
#pragma unroll
    for (int k = 0; k < 8; k++) {
        int i = base + k;
        if (i < N_TOT) g_off[i] = run;
        run += v[k];
    }
    if (tid == 255) g_part[blockIdx.x] = s[255];
}

__global__ __launch_bounds__(128) void scan_b_kernel() {
    __shared__ int s[128];
    int tid = threadIdx.x;
    int v = (tid < SCAN_BLOCKS) ? g_part[tid] : 0;
    s[tid] = v;
    __syncthreads();
    for (int off = 1; off < 128; off <<= 1) {
        int t = (tid >= off) ? s[tid - off] : 0;
        __syncthreads();
        s[tid] += t;
        __syncthreads();
    }
    if (tid < SCAN_BLOCKS) g_part[tid] = s[tid] - v;   // exclusive
    if (tid == 127) g_off[N_TOT] = s[127];
}

__global__ void scan_c_kernel() {
    int i = blockIdx.x * blockDim.x + threadIdx.x;
    if (i >= N_TOT) return;
    int o = g_off[i] + g_part[i / SCAN_CHUNK];
    g_off[i] = o;
    g_pos[i] = o;
}

__global__ void fill_kernel(const int* __restrict__ esrc,
                            const int* __restrict__ edst) {
    int base = (blockIdx.x * blockDim.x + threadIdx.x) * 4;
#pragma unroll
    for (int k = 0; k < 4; k++) {
        int i = base + k;
        if (i < TOTAL_E) {
            int et = i / N_EDGES;
            int d = __ldg(&edst[i]);
            int s = __ldg(&esrc[i]);
            int p = atomicAdd(&g_pos[et * N_NODES + d], 1);
            g_eidx[p] = s;
        }
    }
}

// ---------------------------------------------------------------------------
// bf16-split GEMM helpers
// ---------------------------------------------------------------------------
#define MMA_BF16(D, A, B)                                                     \
    asm volatile(                                                             \
        "mma.sync.aligned.m16n8k16.row.col.f32.bf16.bf16.f32 "                \
        "{%0,%1,%2,%3}, {%4,%5,%6,%7}, {%8,%9}, {%0,%1,%2,%3};"               \
        : "+f"(D[0]), "+f"(D[1]), "+f"(D[2]), "+f"(D[3])                      \
        : "r"(A[0]), "r"(A[1]), "r"(A[2]), "r"(A[3]), "r"(B[0]), "r"(B[1]))

__device__ __forceinline__ void bf16_split2(float a, float b,
                                            uint32_t& hi, uint32_t& lo) {
    __nv_bfloat162 h, l;
    h.x = __float2bfloat16(a);
    h.y = __float2bfloat16(b);
    l.x = __float2bfloat16(a - __bfloat162float(h.x));
    l.y = __float2bfloat16(b - __bfloat162float(h.y));
    hi = *(uint32_t*)&h;
    lo = *(uint32_t*)&l;
}

#define PS 12   // pair-stride: 8 k-pairs + 4 pad

// ---------------------------------------------------------------------------
// Per-etype GEMM: Wh[et] = x @ W[et], split-bf16 (3x m16n8k16 per k-tile).
// ---------------------------------------------------------------------------
__global__ __launch_bounds__(256, 2) void gemm_kernel(const float* __restrict__ x,
                                                      const float* __restrict__ W,
                                                      int et) {
    const int m0 = blockIdx.x * 128;
    const int tid = threadIdx.x;
    const int wid = tid >> 5;
    const int lane = tid & 31;
    const int m_off = (wid >> 1) * 32;
    const int n_off = (wid & 1) * 64;
    const int gq = lane >> 2;
    const int tg = lane & 3;

    __shared__ uint32_t Ah[128 * PS];
    __shared__ uint32_t Al[128 * PS];
    __shared__ uint32_t Bh[128 * PS];
    __shared__ uint32_t Bl[128 * PS];

    const float* Wt = W + (size_t)et * IN_SIZE * OUT_SIZE;

    float acc[2][8][4];
#pragma unroll
    for (int i = 0; i < 2; i++)
#pragma unroll
        for (int j = 0; j < 8; j++)
#pragma unroll
            for (int c = 0; c < 4; c++) acc[i][j][c] = 0.0f;

    const int wn = tid & 127;
    const int wkh = tid >> 7;

    for (int k0 = 0; k0 < IN_SIZE; k0 += 16) {
#pragma unroll
        for (int i = 0; i < 2; i++) {
            int f4 = tid + i * 256;
            int row = f4 >> 2;
            int kc = (f4 & 3) * 4;
            int gm = m0 + row;
            float4 v = make_float4(0.f, 0.f, 0.f, 0.f);
            if (gm < N_NODES) v = *(const float4*)&x[(size_t)gm * IN_SIZE + k0 + kc];
            uint32_t h0, l0, h1, l1;
            bf16_split2(v.x, v.y, h0, l0);
            bf16_split2(v.z, v.w, h1, l1);
            int p = row * PS + (kc >> 1);
            Ah[p] = h0; Ah[p + 1] = h1;
            Al[p] = l0; Al[p + 1] = l1;
        }
        {
            float w[8];
#pragma unroll
            for (int i = 0; i < 8; i++)
                w[i] = __ldg(&Wt[(size_t)(k0 + wkh * 8 + i) * OUT_SIZE + wn]);
            int p = wn * PS + wkh * 4;
#pragma unroll
            for (int q = 0; q < 4; q++) {
                uint32_t h, l;
                bf16_split2(w[2 * q], w[2 * q + 1], h, l);
                Bh[p + q] = h;
                Bl[p + q] = l;
            }
        }
        __syncthreads();

        uint32_t ahi[2][4], alo[2][4];
#pragma unroll
        for (int mf = 0; mf < 2; mf++) {
            int r = (m_off + mf * 16 + gq) * PS;
            ahi[mf][0] = Ah[r + tg];
            ahi[mf][1] = Ah[r + 8 * PS + tg];
            ahi[mf][2] = Ah[r + 4 + tg];
            ahi[mf][3] = Ah[r + 8 * PS + 4 + tg];
            alo[mf][0] = Al[r + tg];
            alo[mf][1] = Al[r + 8 * PS + tg];
            alo[mf][2] = Al[r + 4 + tg];
            alo[mf][3] = Al[r + 8 * PS + 4 + tg];
        }
#pragma unroll
        for (int nf = 0; nf < 8; nf++) {
            int n = (n_off + nf * 8 + gq) * PS;
            uint32_t bhi[2], blo[2];
            bhi[0] = Bh[n + tg];
            bhi[1] = Bh[n + 4 + tg];
            blo[0] = Bl[n + tg];
            blo[1] = Bl[n + 4 + tg];
#pragma unroll
            for (int mf = 0; mf < 2; mf++) {
                MMA_BF16(acc[mf][nf], ahi[mf], bhi);
                MMA_BF16(acc[mf][nf], ahi[mf], blo);
                MMA_BF16(acc[mf][nf], alo[mf], bhi);
            }
        }
        __syncthreads();
    }

    __half* dst = g_Wh + (size_t)et * N_NODES * OUT_SIZE;
#pragma unroll
    for (int mf = 0; mf < 2; mf++) {
#pragma unroll
        for (int nf = 0; nf < 8; nf++) {
            int row = m0 + m_off + mf * 16 + gq;
            int col = n_off + nf * 8 + tg * 2;
            if (row < N_NODES) {
                *(__half2*)&dst[(size_t)row * OUT_SIZE + col] =
                    __floats2half2_rn(acc[mf][nf][0], acc[mf][nf][1]);
            }
            if (row + 8 < N_NODES) {
                *(__half2*)&dst[(size_t)(row + 8) * OUT_SIZE + col] =
                    __floats2half2_rn(acc[mf][nf][2], acc[mf][nf][3]);
            }
        }
    }
}

// ---------------------------------------------------------------------------
// Per-etype gather + mean + bias: 16-deep MLP, then 8, then 1. (round-10 exact)
// ---------------------------------------------------------------------------
__global__ __launch_bounds__(256) void gather_kernel(float* __restrict__ out,
                                                     const float* __restrict__ b,
                                                     int et) {
    const int wid = threadIdx.x >> 5;
    const int lane = threadIdx.x & 31;
    const int n = blockIdx.x * 8 + wid;
    if (n >= N_NODES) return;

    const int base = et * N_NODES + n;
    const int beg = __ldg(&g_off[base]);
    const int end = __ldg(&g_off[base + 1]);

    const __half* wh = g_Wh + (size_t)et * N_NODES * OUT_SIZE;
    float4 a0 = make_float4(0.f, 0.f, 0.f, 0.f);
    float4 a1 = make_float4(0.f, 0.f, 0.f, 0.f);

#define ACC(A, U)                                                            \
    {                                                                        \
        float2 f0 = __half22float2(*(const __half2*)&U.x);                   \
        float2 f1 = __half22float2(*(const __half2*)&U.y);                   \
        A.x += f0.x; A.y += f0.y; A.z += f1.x; A.w += f1.y;                  \
    }

    int j = beg;
    for (; j + 16 <= end; j += 16) {
        int s[16];
#pragma unroll
        for (int k = 0; k < 16; k++) s[k] = __ldg(&g_eidx[j + k]);
        uint2 u[16];
#pragma unroll
        for (int k = 0; k < 16; k++)
            u[k] = __ldg((const uint2*)&wh[(size_t)s[k] * OUT_SIZE + lane * 4]);
#pragma unroll
        for (int k = 0; k < 8; k++) ACC(a0, u[k])
#pragma unroll
        for (int k = 8; k < 16; k++) ACC(a1, u[k])
    }
    for (; j + 8 <= end; j += 8) {
        int s[8];
#pragma unroll
        for (int k = 0; k < 8; k++) s[k] = __ldg(&g_eidx[j + k]);
        uint2 u[8];
#pragma unroll
        for (int k = 0; k < 8; k++)
            u[k] = __ldg((const uint2*)&wh[(size_t)s[k] * OUT_SIZE + lane * 4]);
#pragma unroll
        for (int k = 0; k < 4; k++) ACC(a0, u[k])
#pragma unroll
        for (int k = 4; k < 8; k++) ACC(a1, u[k])
    }
    for (; j < end; j++) {
        int s = __ldg(&g_eidx[j]);
        uint2 u = __ldg((const uint2*)&wh[(size_t)s * OUT_SIZE + lane * 4]);
        ACC(a0, u)
    }
#undef ACC
    a0.x += a1.x; a0.y += a1.y; a0.z += a1.z; a0.w += a1.w;

    float4 r;
    int cnt = end - beg;
    if (cnt > 0) {
        float inv = 1.0f / (float)cnt;
        float4 bb = __ldg(&((const float4*)b)[et * 32 + lane]);
        r.x = a0.x * inv + bb.x;
        r.y = a0.y * inv + bb.y;
        r.z = a0.z * inv + bb.z;
        r.w = a0.w * inv + bb.w;
    } else {
        r = make_float4(0.f, 0.f, 0.f, 0.f);
    }
    ((float4*)out)[((size_t)n * N_ET + et) * 32 + lane] = r;
}

// ---------------------------------------------------------------------------
// Round-10 schedule + split histogram (stream 0 does half the hist while it
// would otherwise idle before the gemms):
//   s_csr    : hist_a -> (wait hist_b) scan_a -> scan_b -> scan_c -> fill [ev_fill]
//              -> (wait gemm0) gather0 -> gather1
//   stream 0 : hist_b [ev_hb] -> gemm0 [ev_g0] -> gemm1 -> gemm2
//              -> (wait fill) gather2
// ---------------------------------------------------------------------------
extern "C" void kernel_launch(void* const* d_in, const int* in_sizes, int n_in,
                              void* d_out, int out_size) {
    const float* x    = (const float*)d_in[0];
    const int*   esrc = (const int*)d_in[1];
    const int*   edst = (const int*)d_in[2];
    const float* W    = (const float*)d_in[3];
    const float* b    = (const float*)d_in[4];
    float* out = (float*)d_out;

    static cudaStream_t s_csr = nullptr;
    static cudaEvent_t ev_fork = nullptr, ev_hb = nullptr, ev_fill = nullptr;
    static cudaEvent_t ev_g0 = nullptr, ev_done = nullptr;
    if (s_csr == nullptr) {
        cudaStreamCreateWithFlags(&s_csr, cudaStreamNonBlocking);
        cudaEventCreateWithFlags(&ev_fork, cudaEventDisableTiming);
        cudaEventCreateWithFlags(&ev_hb, cudaEventDisableTiming);
        cudaEventCreateWithFlags(&ev_fill, cudaEventDisableTiming);
        cudaEventCreateWithFlags(&ev_g0, cudaEventDisableTiming);
        cudaEventCreateWithFlags(&ev_done, cudaEventDisableTiming);
    }

    const int HIST_HALF_B = (HALF_E / 4 + 255) / 256;   // 1465

    // Fork
    cudaEventRecord(ev_fork, 0);
    cudaStreamWaitEvent(s_csr, ev_fork, 0);

    // Histogram halves on both streams (stream 0 is idle here otherwise)
    hist_kernel<<<HIST_HALF_B, 256, 0, s_csr>>>(edst, 0, HALF_E);
    hist_kernel<<<HIST_HALF_B, 256>>>(edst, HALF_E, TOTAL_E);
    cudaEventRecord(ev_hb, 0);

    // Rest of CSR build on s_csr (needs both hist halves)
    cudaStreamWaitEvent(s_csr, ev_hb, 0);
    scan_a_kernel<<<SCAN_BLOCKS, 256, 0, s_csr>>>();
    scan_b_kernel<<<1, 128, 0, s_csr>>>();
    scan_c_kernel<<<(N_TOT + 255) / 256, 256, 0, s_csr>>>();
    fill_kernel<<<(TOTAL_E / 4 + 255) / 256, 256, 0, s_csr>>>(esrc, edst);
    cudaEventRecord(ev_fill, s_csr);

    // GEMMs on stream 0
    gemm_kernel<<<GEMM_BX, 256>>>(x, W, 0);
    cudaEventRecord(ev_g0, 0);
    gemm_kernel<<<GEMM_BX, 256>>>(x, W, 1);
    gemm_kernel<<<GEMM_BX, 256>>>(x, W, 2);

    // s_csr consumes etypes 0 and 1
    cudaStreamWaitEvent(s_csr, ev_g0, 0);
    gather_kernel<<<(N_NODES + 7) / 8, 256, 0, s_csr>>>(out, b, 0);
    gather_kernel<<<(N_NODES + 7) / 8, 256, 0, s_csr>>>(out, b, 1);
    cudaEventRecord(ev_done, s_csr);

    // stream 0 consumes etype 2
    cudaStreamWaitEvent(0, ev_fill, 0);
    gather_kernel<<<(N_NODES + 7) / 8, 256>>>(out, b, 2);

    // Join
    cudaStreamWaitEvent(0, ev_done, 0);
}